// round 2
// baseline (speedup 1.0000x reference)
#include <cuda_runtime.h>
#include <cstdint>

#define BS   8
#define NN   1024
#define JJ   3
#define FIN  32
#define ROWS (BS*NN)        // 8192
#define RPC  32             // rows per CTA
#define NCTA (ROWS/RPC)     // 256
#define MT   64             // m per tile
#define NTILE (NN/MT)       // 16
#define WPAD 196            // padded WW smem row (192 -> 196), conflict-free
#define WCPAD 98            // padded FC weight row (96 -> 98), 8B aligned

typedef unsigned long long u64;

// scratch (no allocations allowed)
__device__ float g_zbuf[ROWS*64];
__device__ float g_part[NCTA*64];
__device__ float g_psq[NCTA*64];
__device__ float g_scale[64];
__device__ float g_shift[64];

__device__ __forceinline__ u64 pack2(float a, float b){
    u64 r; asm("mov.b64 %0,{%1,%2};" : "=l"(r) : "f"(a), "f"(b)); return r;
}
__device__ __forceinline__ void unpack2(u64 v, float& a, float& b){
    asm("mov.b64 {%0,%1},%2;" : "=f"(a), "=f"(b) : "l"(v));
}
__device__ __forceinline__ u64 fma2(u64 a, u64 b, u64 c){
    u64 d; asm("fma.rn.f32x2 %0,%1,%2,%3;" : "=l"(d) : "l"(a), "l"(b), "l"(c)); return d;
}

struct SmemA {                       // main-loop tiles
    float ws[RPC*WPAD];              // 25088 B
    float xs[MT*FIN];                // 8192 B
};
struct SmemB {                       // epilogue
    float ys[RPC*96];                // 12288 B
    float wc[64*WCPAD];              // 25088 B
    float bias[64];
    float psum[128];
    float psq[128];
};
union SmemU { SmemA a; SmemB b; };   // max ~38.7 KB < 48 KB static limit

__global__ __launch_bounds__(128, 2)
void k_main(const float* __restrict__ WW, const float* __restrict__ x,
            const float* __restrict__ W1, const float* __restrict__ b1,
            const float* __restrict__ W2, const float* __restrict__ b2)
{
    __shared__ SmemU sm;
    const int tid = threadIdx.x;
    const int cta = blockIdx.x;
    const int R0  = cta * RPC;           // global row base; all rows same batch b
    const int b   = R0 / NN;

    const int r  = tid >> 2;             // 0..31  (row within CTA)
    const int fg = tid & 3;              // 0..3   (f-group of 8)

    u64 acc[3][4];
    #pragma unroll
    for (int j = 0; j < 3; j++)
        #pragma unroll
        for (int p = 0; p < 4; p++) acc[j][p] = 0ull;   // bits 0 == (0.f,0.f)

    const float* xb = x + (size_t)b * NN * FIN;

    for (int t = 0; t < NTILE; t++) {
        const int m0 = t * MT;
        // ---- load x tile: MT*FIN = 2048 floats = 512 float4 (16B aligned) ----
        {
            const float4* xg  = (const float4*)(xb + (size_t)m0 * FIN);
            float4*       xs4 = (float4*)sm.a.xs;
            #pragma unroll
            for (int i = 0; i < 4; i++) xs4[tid + i*128] = xg[tid + i*128];
        }
        // ---- load WW tile: RPC rows x 48 float4 each (16B aligned: ((R)*1024+m0)*3 % 4 == 0) ----
        {
            #pragma unroll
            for (int i = 0; i < 12; i++) {
                int idx = tid + i*128;               // < 1536
                int rr = idx / 48, cc = idx % 48;
                const float4* wg = (const float4*)(WW + ((size_t)(R0 + rr) * NN + m0) * JJ);
                *(float4*)&sm.a.ws[rr*WPAD + cc*4] = wg[cc];
            }
        }
        __syncthreads();

        const float* wrow = &sm.a.ws[r * WPAD];
        #pragma unroll 4
        for (int mm = 0; mm < MT; mm++) {
            float w0 = wrow[mm*3 + 0];
            float w1v = wrow[mm*3 + 1];
            float w2v = wrow[mm*3 + 2];
            float4 xa  = *(const float4*)&sm.a.xs[mm*FIN + fg*8];
            float4 xb4 = *(const float4*)&sm.a.xs[mm*FIN + fg*8 + 4];
            u64 x0 = pack2(xa.x, xa.y),  x1 = pack2(xa.z, xa.w);
            u64 x2 = pack2(xb4.x, xb4.y), x3 = pack2(xb4.z, xb4.w);
            u64 wj0 = pack2(w0, w0), wj1 = pack2(w1v, w1v), wj2 = pack2(w2v, w2v);
            acc[0][0] = fma2(wj0, x0, acc[0][0]);
            acc[0][1] = fma2(wj0, x1, acc[0][1]);
            acc[0][2] = fma2(wj0, x2, acc[0][2]);
            acc[0][3] = fma2(wj0, x3, acc[0][3]);
            acc[1][0] = fma2(wj1, x0, acc[1][0]);
            acc[1][1] = fma2(wj1, x1, acc[1][1]);
            acc[1][2] = fma2(wj1, x2, acc[1][2]);
            acc[1][3] = fma2(wj1, x3, acc[1][3]);
            acc[2][0] = fma2(wj2, x0, acc[2][0]);
            acc[2][1] = fma2(wj2, x1, acc[2][1]);
            acc[2][2] = fma2(wj2, x2, acc[2][2]);
            acc[2][3] = fma2(wj2, x3, acc[2][3]);
        }
        __syncthreads();   // everyone done reading tiles before next load / epilogue reuse
    }

    // ================= epilogue: y -> smem, FC, BN partials =================
    #pragma unroll
    for (int j = 0; j < 3; j++)
        #pragma unroll
        for (int p = 0; p < 4; p++) {
            float lo, hi; unpack2(acc[j][p], lo, hi);
            sm.b.ys[r*96 + j*32 + fg*8 + p*2]     = lo;
            sm.b.ys[r*96 + j*32 + fg*8 + p*2 + 1] = hi;
        }
    // FC weights (combined 64x96) + bias
    for (int i = tid; i < 64*96; i += 128) {
        int k = i / 96, c = i % 96;
        sm.b.wc[k*WCPAD + c] = (k < 32) ? W1[k*96 + c] : W2[(k-32)*96 + c];
    }
    if (tid < 32)       sm.b.bias[tid] = b1[tid];
    else if (tid < 64)  sm.b.bias[tid] = b2[tid - 32];
    __syncthreads();

    {
        const int k     = tid & 63;      // output feature
        const int rbase = tid >> 6;      // 0 or 1
        float ls = 0.f, lsq = 0.f;
        const float bk = sm.b.bias[k];
        const u64* wk = (const u64*)&sm.b.wc[k * WCPAD];
        #pragma unroll 1
        for (int i = 0; i < 16; i++) {
            int row = rbase + i*2;
            const u64* yr = (const u64*)&sm.b.ys[row * 96];
            u64 a2 = 0ull;
            #pragma unroll
            for (int ii = 0; ii < 48; ii++) a2 = fma2(yr[ii], wk[ii], a2);
            float lo, hi; unpack2(a2, lo, hi);
            float z = lo + hi + bk;
            if (k < 32) z = fmaxf(z, 0.f);
            g_zbuf[(size_t)(R0 + row) * 64 + k] = z;
            ls  += z;
            lsq += z * z;
        }
        sm.b.psum[tid] = ls;
        sm.b.psq[tid]  = lsq;
    }
    __syncthreads();
    if (tid < 64) {
        g_part[cta*64 + tid] = sm.b.psum[tid] + sm.b.psum[tid + 64];
        g_psq[cta*64 + tid]  = sm.b.psq[tid]  + sm.b.psq[tid + 64];
    }
}

__global__ void k_stats(const float* __restrict__ gamma, const float* __restrict__ beta)
{
    int k = threadIdx.x;
    if (k >= 64) return;
    double s = 0.0, sq = 0.0;
    for (int c = 0; c < NCTA; c++) {
        s  += (double)g_part[c*64 + k];
        sq += (double)g_psq[c*64 + k];
    }
    float mean = (float)(s / (double)ROWS);
    float var  = (float)(sq / (double)ROWS) - mean * mean;
    float sc = gamma[k] * rsqrtf(var + 1e-5f);
    g_scale[k] = sc;
    g_shift[k] = beta[k] - mean * sc;
}

__global__ __launch_bounds__(256)
void k_norm(float* __restrict__ out)
{
    __shared__ float sc[64], sh[64];
    int tid = threadIdx.x;
    if (tid < 64) { sc[tid] = g_scale[tid]; sh[tid] = g_shift[tid]; }
    __syncthreads();
    int i = blockIdx.x * 256 + tid;                 // float4 index, 131072 total
    float4 z = ((const float4*)g_zbuf)[i];
    int kb = (i & 15) * 4;                          // 16 float4 groups per 64-wide row
    float4 o;
    o.x = z.x * sc[kb+0] + sh[kb+0];
    o.y = z.y * sc[kb+1] + sh[kb+1];
    o.z = z.z * sc[kb+2] + sh[kb+2];
    o.w = z.w * sc[kb+3] + sh[kb+3];
    ((float4*)out)[i] = o;
}

extern "C" void kernel_launch(void* const* d_in, const int* in_sizes, int n_in,
                              void* d_out, int out_size)
{
    const float* WW    = (const float*)d_in[0];
    const float* x     = (const float*)d_in[1];
    const float* W1    = (const float*)d_in[2];
    const float* b1    = (const float*)d_in[3];
    const float* W2    = (const float*)d_in[4];
    const float* b2    = (const float*)d_in[5];
    const float* gamma = (const float*)d_in[6];
    const float* beta  = (const float*)d_in[7];
    float* out = (float*)d_out;

    k_main <<<NCTA, 128>>>(WW, x, W1, b1, W2, b2);
    k_stats<<<1, 64>>>(gamma, beta);
    k_norm <<<ROWS*64/(256*4), 256>>>(out);
}

// round 3
// speedup vs baseline: 1.3160x; 1.3160x over previous
#include <cuda_runtime.h>
#include <cstdint>

#define BS   8
#define NN   1024
#define JJ   3
#define FIN  32
#define ROWS (BS*NN)        // 8192
#define RPC  16             // rows per CTA
#define NCTA (ROWS/RPC)     // 512
#define MT   64             // m per tile
#define NTILE (NN/MT)       // 16
#define WP2  196            // ws2 row stride in u64 (192 used), bank-skewed
#define XPAD 36             // xs row stride in floats (32 used), bank-skewed
#define WCPAD 98

typedef unsigned long long u64;

// scratch (no allocations allowed)
__device__ float g_zbuf[ROWS*64];
__device__ float g_part[NCTA*64];
__device__ float g_psq[NCTA*64];
__device__ float g_scale[64];
__device__ float g_shift[64];

__device__ __forceinline__ u64 pack2(float a, float b){
    u64 r; asm("mov.b64 %0,{%1,%2};" : "=l"(r) : "f"(a), "f"(b)); return r;
}
__device__ __forceinline__ void unpack2(u64 v, float& a, float& b){
    asm("mov.b64 {%0,%1},%2;" : "=f"(a), "=f"(b) : "l"(v));
}
__device__ __forceinline__ u64 fma2(u64 a, u64 b, u64 c){
    u64 d; asm("fma.rn.f32x2 %0,%1,%2,%3;" : "=l"(d) : "l"(a), "l"(b), "l"(c)); return d;
}

struct SmemA {                        // main loop
    u64   ws2[RPC*WP2];               // 25088 B : (w,w) pairs, row-major [r][m*3+j]
    float xs[MT*XPAD];                // 9216 B  : [m][f] padded
};
struct SmemB {                        // epilogue
    float ys[RPC*96];                 // 6144 B
    float wc[64*WCPAD];               // 25088 B
    float bias[64];
    float psum[128];
    float psq[128];
};
union __align__(16) SmemU { SmemA a; SmemB b; };

__global__ __launch_bounds__(128, 4)
void k_main(const float* __restrict__ WW, const float* __restrict__ x,
            const float* __restrict__ W1, const float* __restrict__ b1,
            const float* __restrict__ W2, const float* __restrict__ b2)
{
    __shared__ SmemU sm;
    const int tid = threadIdx.x;
    const int cta = blockIdx.x;
    const int R0  = cta * RPC;
    const int b   = R0 / NN;

    // thread owns: row r (0..15), m-parity mh (0/1), f-group fg (0..3, 8 f each)
    const int fg = tid & 3;
    const int mh = (tid >> 2) & 1;
    const int r  = tid >> 3;

    u64 acc[3][4];
    #pragma unroll
    for (int j = 0; j < 3; j++)
        #pragma unroll
        for (int p = 0; p < 4; p++) acc[j][p] = 0ull;

    const float* xb = x + (size_t)b * NN * FIN;

    // tile-invariant load assignments
    // ws: 768 float4 per tile -> 6 per thread
    int w_rr[6], w_cc[6];
    #pragma unroll
    for (int k = 0; k < 6; k++) { int idx = tid + k*128; w_rr[k] = idx / 48; w_cc[k] = idx % 48; }
    // xs: 512 float4 per tile -> 4 per thread
    int x_mm[4], x_cc[4];
    #pragma unroll
    for (int k = 0; k < 4; k++) { int idx = tid + k*128; x_mm[k] = idx >> 3; x_cc[k] = idx & 7; }

    float4 wreg[6], xreg[4];

    auto loadg = [&](int t){
        const int m0 = t * MT;
        #pragma unroll
        for (int k = 0; k < 6; k++) {
            const float4* wg = (const float4*)(WW + ((size_t)(R0 + w_rr[k]) * NN + m0) * JJ);
            wreg[k] = __ldg(&wg[w_cc[k]]);
        }
        #pragma unroll
        for (int k = 0; k < 4; k++) {
            const float4* xg = (const float4*)(xb + (size_t)(m0 + x_mm[k]) * FIN);
            xreg[k] = __ldg(&xg[x_cc[k]]);
        }
    };
    auto store_s = [&](){
        #pragma unroll
        for (int k = 0; k < 6; k++) {
            u64* dst = &sm.a.ws2[w_rr[k]*WP2 + w_cc[k]*4];
            float4 g = wreg[k];
            dst[0] = pack2(g.x, g.x);
            dst[1] = pack2(g.y, g.y);
            dst[2] = pack2(g.z, g.z);
            dst[3] = pack2(g.w, g.w);
        }
        #pragma unroll
        for (int k = 0; k < 4; k++)
            *(float4*)&sm.a.xs[x_mm[k]*XPAD + x_cc[k]*4] = xreg[k];
    };

    loadg(0); store_s();
    __syncthreads();

    const u64* wbase = &sm.a.ws2[r * WP2];
    const int  xoff  = fg * 8;

    for (int t = 0; t < NTILE; t++) {
        if (t + 1 < NTILE) loadg(t + 1);

        #pragma unroll 8
        for (int k = 0; k < 32; k++) {
            const int mm = 2*k + mh;
            u64 w0 = wbase[mm*3 + 0];
            u64 w1 = wbase[mm*3 + 1];
            u64 w2 = wbase[mm*3 + 2];
            ulonglong2 p0 = *(const ulonglong2*)&sm.a.xs[mm*XPAD + xoff];
            ulonglong2 p1 = *(const ulonglong2*)&sm.a.xs[mm*XPAD + xoff + 4];
            acc[0][0] = fma2(w0, p0.x, acc[0][0]);
            acc[0][1] = fma2(w0, p0.y, acc[0][1]);
            acc[0][2] = fma2(w0, p1.x, acc[0][2]);
            acc[0][3] = fma2(w0, p1.y, acc[0][3]);
            acc[1][0] = fma2(w1, p0.x, acc[1][0]);
            acc[1][1] = fma2(w1, p0.y, acc[1][1]);
            acc[1][2] = fma2(w1, p1.x, acc[1][2]);
            acc[1][3] = fma2(w1, p1.y, acc[1][3]);
            acc[2][0] = fma2(w2, p0.x, acc[2][0]);
            acc[2][1] = fma2(w2, p0.y, acc[2][1]);
            acc[2][2] = fma2(w2, p1.x, acc[2][2]);
            acc[2][3] = fma2(w2, p1.y, acc[2][3]);
        }
        __syncthreads();
        if (t + 1 < NTILE) { store_s(); __syncthreads(); }
    }

    // ============ epilogue: combine mh halves -> ys, FC, BN partials ============
    if (mh == 0) {
        #pragma unroll
        for (int j = 0; j < 3; j++)
            #pragma unroll
            for (int p = 0; p < 4; p++) {
                float lo, hi; unpack2(acc[j][p], lo, hi);
                sm.b.ys[r*96 + j*32 + fg*8 + p*2]     = lo;
                sm.b.ys[r*96 + j*32 + fg*8 + p*2 + 1] = hi;
            }
    }
    // FC weights + bias (regions beyond ys; safe after final sync above)
    for (int i = tid; i < 64*96; i += 128) {
        int k = i / 96, c = i % 96;
        sm.b.wc[k*WCPAD + c] = (k < 32) ? W1[k*96 + c] : W2[(k-32)*96 + c];
    }
    if (tid < 32)       sm.b.bias[tid] = b1[tid];
    else if (tid < 64)  sm.b.bias[tid] = b2[tid - 32];
    __syncthreads();
    if (mh == 1) {
        #pragma unroll
        for (int j = 0; j < 3; j++)
            #pragma unroll
            for (int p = 0; p < 4; p++) {
                float lo, hi; unpack2(acc[j][p], lo, hi);
                sm.b.ys[r*96 + j*32 + fg*8 + p*2]     += lo;
                sm.b.ys[r*96 + j*32 + fg*8 + p*2 + 1] += hi;
            }
    }
    __syncthreads();

    {
        const int k  = tid & 63;
        const int rh = tid >> 6;          // 0/1
        float ls = 0.f, lsq = 0.f;
        const float bk = sm.b.bias[k];
        const u64* wk = (const u64*)&sm.b.wc[k * WCPAD];
        #pragma unroll 1
        for (int i = 0; i < 8; i++) {
            int row = rh + 2*i;
            const u64* yr = (const u64*)&sm.b.ys[row * 96];
            u64 a2 = 0ull;
            #pragma unroll
            for (int ii = 0; ii < 48; ii++) a2 = fma2(yr[ii], wk[ii], a2);
            float lo, hi; unpack2(a2, lo, hi);
            float z = lo + hi + bk;
            if (k < 32) z = fmaxf(z, 0.f);
            g_zbuf[(size_t)(R0 + row) * 64 + k] = z;
            ls  += z;
            lsq += z * z;
        }
        sm.b.psum[tid] = ls;
        sm.b.psq[tid]  = lsq;
    }
    __syncthreads();
    if (tid < 64) {
        g_part[cta*64 + tid] = sm.b.psum[tid] + sm.b.psum[tid + 64];
        g_psq[cta*64 + tid]  = sm.b.psq[tid]  + sm.b.psq[tid + 64];
    }
}

__global__ __launch_bounds__(128)
void k_stats(const float* __restrict__ gamma, const float* __restrict__ beta)
{
    __shared__ float rs[128], rq[128];
    const int k = blockIdx.x;
    const int tid = threadIdx.x;
    float s = 0.f, sq = 0.f;
    #pragma unroll
    for (int i = 0; i < NCTA/128; i++) {
        int c = tid + i*128;
        s  += g_part[c*64 + k];
        sq += g_psq[c*64 + k];
    }
    rs[tid] = s; rq[tid] = sq;
    __syncthreads();
    for (int off = 64; off >= 32; off >>= 1) {
        if (tid < off) { rs[tid] += rs[tid+off]; rq[tid] += rq[tid+off]; }
        __syncthreads();
    }
    if (tid < 32) {
        s = rs[tid]; sq = rq[tid];
        #pragma unroll
        for (int off = 16; off > 0; off >>= 1) {
            s  += __shfl_down_sync(0xffffffffu, s, off);
            sq += __shfl_down_sync(0xffffffffu, sq, off);
        }
        if (tid == 0) {
            float mean = s / (float)ROWS;
            float var  = sq / (float)ROWS - mean * mean;
            float sc = gamma[k] * rsqrtf(var + 1e-5f);
            g_scale[k] = sc;
            g_shift[k] = beta[k] - mean * sc;
        }
    }
}

__global__ __launch_bounds__(256)
void k_norm(float* __restrict__ out)
{
    __shared__ float sc[64], sh[64];
    int tid = threadIdx.x;
    if (tid < 64) { sc[tid] = g_scale[tid]; sh[tid] = g_shift[tid]; }
    __syncthreads();
    int i = blockIdx.x * 256 + tid;                 // float4 index, 131072 total
    float4 z = ((const float4*)g_zbuf)[i];
    int kb = (i & 15) * 4;
    float4 o;
    o.x = z.x * sc[kb+0] + sh[kb+0];
    o.y = z.y * sc[kb+1] + sh[kb+1];
    o.z = z.z * sc[kb+2] + sh[kb+2];
    o.w = z.w * sc[kb+3] + sh[kb+3];
    ((float4*)out)[i] = o;
}

extern "C" void kernel_launch(void* const* d_in, const int* in_sizes, int n_in,
                              void* d_out, int out_size)
{
    const float* WW    = (const float*)d_in[0];
    const float* x     = (const float*)d_in[1];
    const float* W1    = (const float*)d_in[2];
    const float* b1    = (const float*)d_in[3];
    const float* W2    = (const float*)d_in[4];
    const float* b2    = (const float*)d_in[5];
    const float* gamma = (const float*)d_in[6];
    const float* beta  = (const float*)d_in[7];
    float* out = (float*)d_out;

    k_main <<<NCTA, 128>>>(WW, x, W1, b1, W2, b2);
    k_stats<<<64, 128>>>(gamma, beta);
    k_norm <<<ROWS*64/(256*4), 256>>>(out);
}